// round 4
// baseline (speedup 1.0000x reference)
#include <cuda_runtime.h>
#include <math.h>

#define NSEQ 64
static constexpr int LA  = 2305;   // run0 length (1 gt + 48*48)
static constexpr int LB  = 3073;   // run1/2 length (1 gt + 128*24)
static constexpr int LPA = 2336;   // padded strides (mult of 32)
static constexpr int LPB = 3104;

// ---------- scratch (device globals; allocation-free) ----------
__device__ __align__(16) float gA_xz [NSEQ*LA*128];
__device__ __align__(16) float gA_dtT[NSEQ*64*LPA];
__device__ __align__(16) float gA_xsT[NSEQ*64*LPA];
__device__ __align__(16) float gA_zsT[NSEQ*64*LPA];
__device__ __align__(16) float gA_bcT[NSEQ*32*LPA];
__device__ __align__(16) float gA_y  [NSEQ*(LA-1)*64];
__device__ __align__(16) float gA_o  [NSEQ*(LA-1)*32];

__device__ __align__(16) float gB_xz0 [NSEQ*LB*96];
__device__ __align__(16) float gB_dtT0[NSEQ*48*LPB];
__device__ __align__(16) float gB_xsT0[NSEQ*48*LPB];
__device__ __align__(16) float gB_zsT0[NSEQ*48*LPB];
__device__ __align__(16) float gB_bcT0[NSEQ*32*LPB];
__device__ __align__(16) float gB_y0  [NSEQ*(LB-1)*48];
__device__ __align__(16) float gB_o0  [NSEQ*(LB-1)*24];

__device__ __align__(16) float gB_xz1 [NSEQ*LB*96];
__device__ __align__(16) float gB_dtT1[NSEQ*48*LPB];
__device__ __align__(16) float gB_xsT1[NSEQ*48*LPB];
__device__ __align__(16) float gB_zsT1[NSEQ*48*LPB];
__device__ __align__(16) float gB_bcT1[NSEQ*32*LPB];
__device__ __align__(16) float gB_y1  [NSEQ*(LB-1)*48];
__device__ __align__(16) float gB_o1  [NSEQ*(LB-1)*24];

__device__ __forceinline__ float warp_sum(float v){
  v += __shfl_xor_sync(0xffffffffu, v, 16);
  v += __shfl_xor_sync(0xffffffffu, v, 8);
  v += __shfl_xor_sync(0xffffffffu, v, 4);
  v += __shfl_xor_sync(0xffffffffu, v, 2);
  v += __shfl_xor_sync(0xffffffffu, v, 1);
  return v;
}
__device__ __forceinline__ float silu_f(float x){
  return __fdividef(x, 1.f + __expf(-x));
}

// ============ K1: gather + layernorm + in_proj ============
// RUN: 0 = pixel-shuffle run, 1 = B runs (blockIdx.z picks 0/1 variant).
template<int RUN>
__global__ void __launch_bounds__(128) k_inproj(
    const float* __restrict__ x, const float* __restrict__ nw,
    const float* __restrict__ nb, const float* __restrict__ gt,
    const float* __restrict__ Win)
{
  constexpr int DM  = (RUN==0)?32:24;
  constexpr int DXZ = (RUN==0)?128:96;
  constexpr int LF  = (RUN==0)?LA:LB;
  constexpr int KO  = DXZ/32;
  __shared__ float Wt[DM*DXZ];                    // [d][o]
  __shared__ __align__(16) float vsh[4][DM][8];

  int tid = threadIdx.x;
  for (int i = tid; i < DXZ*DM; i += 128){
    int o = i / DM, d = i - o*DM;
    Wt[d*DXZ + o] = Win[i];
  }
  int w = tid >> 5, lane = tid & 31;
  int n = blockIdx.y, bh = n >> 3, bw = n & 7;
  int zz = (RUN==0)?0:blockIdx.z;
  int t0 = (blockIdx.x*4 + w)*8;

  float v[8];
  #pragma unroll
  for (int tok = 0; tok < 8; tok++){
    int t = t0 + tok; float val = 0.f;
    if (lane < DM && t < LF){
      if (t == 0) val = gt[lane];
      else {
        int q = t - 1, addr;
        if (RUN == 0){
          int row = q / 48, col = q - row*48;
          int i0 = row >> 1, r1 = row & 1, j0 = col >> 1, r2 = col & 1;
          addr = (lane*4 + r1*2 + r2)*36864 + (bh*24 + i0)*192 + bw*24 + j0;
        } else {
          int c = q / 24, p = q - c*24;
          if (zz == 0) addr = c*36864 + (bh*24 + lane)*192 + bw*24 + p;
          else         addr = c*36864 + (bh*24 + p)*192 + bw*24 + lane;
        }
        val = __ldg(x + addr);
      }
    }
    v[tok] = val;
  }
  float nwv = (lane < DM) ? nw[lane] : 0.f;
  float nbv = (lane < DM) ? nb[lane] : 0.f;
  #pragma unroll
  for (int tok = 0; tok < 8; tok++){
    float s  = warp_sum(v[tok]);
    float s2 = warp_sum(v[tok]*v[tok]);
    float m  = s * (1.f/DM);
    float var = s2 * (1.f/DM) - m*m;
    float vn = (v[tok] - m) * rsqrtf(var + 1e-5f) * nwv + nbv;
    if (lane < DM) vsh[w][lane][tok] = vn;
  }
  __syncthreads();

  float acc[KO][8];
  #pragma unroll
  for (int k = 0; k < KO; k++)
    #pragma unroll
    for (int j = 0; j < 8; j++) acc[k][j] = 0.f;

  #pragma unroll 4
  for (int d = 0; d < DM; d++){
    float4 v0 = ((const float4*)vsh[w][d])[0];
    float4 v1 = ((const float4*)vsh[w][d])[1];
    #pragma unroll
    for (int k = 0; k < KO; k++){
      float wv = Wt[d*DXZ + lane + 32*k];
      acc[k][0] = fmaf(wv, v0.x, acc[k][0]);
      acc[k][1] = fmaf(wv, v0.y, acc[k][1]);
      acc[k][2] = fmaf(wv, v0.z, acc[k][2]);
      acc[k][3] = fmaf(wv, v0.w, acc[k][3]);
      acc[k][4] = fmaf(wv, v1.x, acc[k][4]);
      acc[k][5] = fmaf(wv, v1.y, acc[k][5]);
      acc[k][6] = fmaf(wv, v1.z, acc[k][6]);
      acc[k][7] = fmaf(wv, v1.w, acc[k][7]);
    }
  }
  float* xz = (RUN==0) ? gA_xz : (zz==0 ? gB_xz0 : gB_xz1);
  #pragma unroll
  for (int tok = 0; tok < 8; tok++){
    int t = t0 + tok;
    if (t < LF){
      float* op = xz + (n*LF + t)*DXZ + lane;
      #pragma unroll
      for (int k = 0; k < KO; k++) op[32*k] = acc[k][tok];
    }
  }
}

// ============ K2: conv + silu + x_proj + dt ; smem-transposed, coalesced flush ============
// 256 threads, 32-token tile per block. RUN: 0 = A, 1 = B (z picks variant).
template<int RUN>
__global__ void __launch_bounds__(256) k_convxp(
  const float* __restrict__ convw, const float* __restrict__ convb,
  const float* __restrict__ Wx,    const float* __restrict__ dtw,
  const float* __restrict__ dtb)
{
  constexpr int DIN = (RUN==0)?64:48;
  constexpr int DXZ = 2*DIN;
  constexpr int LF  = (RUN==0)?LA:LB;
  constexpr int LFP = (RUN==0)?LPA:LPB;
  int zz = (RUN==0)?0:blockIdx.z;
  const float* xz = (RUN==0) ? gA_xz : (zz==0 ? gB_xz0 : gB_xz1);
  float* xsT = (RUN==0) ? gA_xsT : (zz==0 ? gB_xsT0 : gB_xsT1);
  float* zsT = (RUN==0) ? gA_zsT : (zz==0 ? gB_zsT0 : gB_zsT1);
  float* dtT = (RUN==0) ? gA_dtT : (zz==0 ? gB_dtT0 : gB_dtT1);
  float* bcT = (RUN==0) ? gA_bcT : (zz==0 ? gB_bcT0 : gB_bcT1);

  __shared__ float Wxt[DIN*34];        // [d][o]
  __shared__ float xs_s[DIN][33];
  __shared__ float zs_s[DIN][33];
  __shared__ float dt_s[DIN][33];
  __shared__ float bc_s[32][33];

  int tid = threadIdx.x;
  for (int i = tid; i < 34*DIN; i += 256){
    int o = i / DIN, d = i - o*DIN;
    Wxt[d*34 + o] = Wx[i];
  }
  int w = tid >> 5, lane = tid & 31;
  int n = blockIdx.y;
  int tile0 = blockIdx.x*32;
  int t0 = tile0 + w*4;

  float cw[2][4], cb[2], w0c[2], w1c[2], db[2];
  #pragma unroll
  for (int kk = 0; kk < 2; kk++){
    int ch = lane + 32*kk;
    bool ok = ch < DIN;
    #pragma unroll
    for (int k = 0; k < 4; k++) cw[kk][k] = ok ? convw[ch*4+k] : 0.f;
    cb[kk]  = ok ? convb[ch]   : 0.f;
    w0c[kk] = ok ? dtw[ch*2+0] : 0.f;
    w1c[kk] = ok ? dtw[ch*2+1] : 0.f;
    db[kk]  = ok ? dtb[ch]     : 0.f;
  }
  #pragma unroll
  for (int tok = 0; tok < 4; tok++){
    int t = t0 + tok;
    bool valid = t < LF;
    #pragma unroll
    for (int kk = 0; kk < 2; kk++){
      int ch = lane + 32*kk;
      if (ch < DIN){
        float a = cb[kk];
        float zval = 0.f;
        if (valid){
          #pragma unroll
          for (int k = 0; k < 4; k++){
            int ts = t + k - 3;
            if (ts >= 0) a = fmaf(xz[(n*LF + ts)*DXZ + ch], cw[kk][k], a);
          }
          zval = xz[(n*LF + t)*DXZ + DIN + ch];
        }
        xs_s[ch][w*4+tok] = silu_f(a);
        zs_s[ch][w*4+tok] = silu_f(zval);
      }
    }
  }
  __syncthreads();   // Wxt + xs_s ready

  float acc[4]  = {0,0,0,0};
  float acc2[4] = {0,0,0,0};
  #pragma unroll 8
  for (int d = 0; d < DIN; d++){
    float wv = Wxt[d*34 + lane];
    float x0 = xs_s[d][w*4+0];
    float x1 = xs_s[d][w*4+1];
    float x2 = xs_s[d][w*4+2];
    float x3 = xs_s[d][w*4+3];
    acc[0] = fmaf(wv, x0, acc[0]);
    acc[1] = fmaf(wv, x1, acc[1]);
    acc[2] = fmaf(wv, x2, acc[2]);
    acc[3] = fmaf(wv, x3, acc[3]);
    if (lane < 2){
      float w2 = Wxt[d*34 + 32 + lane];
      acc2[0] = fmaf(w2, x0, acc2[0]);
      acc2[1] = fmaf(w2, x1, acc2[1]);
      acc2[2] = fmaf(w2, x2, acc2[2]);
      acc2[3] = fmaf(w2, x3, acc2[3]);
    }
  }
  #pragma unroll
  for (int tok = 0; tok < 4; tok++){
    float d0 = __shfl_sync(0xffffffffu, acc[tok], 0);
    float d1 = __shfl_sync(0xffffffffu, acc[tok], 1);
    #pragma unroll
    for (int kk = 0; kk < 2; kk++){
      int ch = lane + 32*kk;
      if (ch < DIN){
        float r = fmaf(w0c[kk], d0, fmaf(w1c[kk], d1, db[kk]));
        dt_s[ch][w*4+tok] = fmaxf(r, 0.f) + __logf(1.f + __expf(-fabsf(r)));
      }
    }
    // B/C comps: lanes 2..33 -> comps 0..31 (lane<2 supplies comps 30,31 via acc2)
    if (lane >= 2) bc_s[lane-2][w*4+tok]  = acc[tok];
    else           bc_s[30+lane][w*4+tok] = acc2[tok];
  }
  __syncthreads();

  // coalesced flush: consecutive threads -> consecutive float4 along t
  for (int i = tid; i < DIN*8; i += 256){
    int ch = i >> 3, v = i & 7;
    int tt = tile0 + 4*v;
    size_t off = (size_t)(n*DIN + ch)*LFP + tt;
    *(float4*)(xsT + off) = make_float4(xs_s[ch][4*v],xs_s[ch][4*v+1],xs_s[ch][4*v+2],xs_s[ch][4*v+3]);
    *(float4*)(zsT + off) = make_float4(zs_s[ch][4*v],zs_s[ch][4*v+1],zs_s[ch][4*v+2],zs_s[ch][4*v+3]);
    *(float4*)(dtT + off) = make_float4(dt_s[ch][4*v],dt_s[ch][4*v+1],dt_s[ch][4*v+2],dt_s[ch][4*v+3]);
  }
  for (int i = tid; i < 32*8; i += 256){
    int cmp = i >> 3, v = i & 7;
    int tt = tile0 + 4*v;
    *(float4*)(bcT + (size_t)(n*32 + cmp)*LFP + tt) =
      make_float4(bc_s[cmp][4*v],bc_s[cmp][4*v+1],bc_s[cmp][4*v+2],bc_s[cmp][4*v+3]);
  }
}

// ============ K3: selective scan, streaming float4 loads ============
template<int L, int DIN, int LFP>
__device__ __forceinline__ void scan_seq(
  const float* __restrict__ dtT, const float* __restrict__ xsT,
  const float* __restrict__ zsT, const float* __restrict__ bcT,
  float* __restrict__ y, const float* __restrict__ alog,
  const float* __restrict__ Dv, int n, int ch2, int lane)
{
  int half = lane >> 4, s = lane & 15;
  int ch = ch2 + half;
  const float* dtp = dtT + (size_t)(n*DIN + ch)*LFP;
  const float* xsp = xsT + (size_t)(n*DIN + ch)*LFP;
  const float* zsp = zsT + (size_t)(n*DIN + ch)*LFP;
  const float* Bp  = bcT + (size_t)(n*32 + s)*LFP;
  const float* Cp  = bcT + (size_t)(n*32 + 16 + s)*LFP;
  float A  = -expf(__ldg(alog + ch*16 + s));
  float Dd = __ldg(Dv + ch);
  float* yp = y + (size_t)n*(L-1)*DIN + ch;
  bool yl = (s == 0);
  float h = 0.f;
  constexpr int NB = (L-1)/4;
  for (int tb = 0; tb < NB; tb++){
    int t = tb*4;
    float4 dq = *(const float4*)(dtp + t);
    float4 uq = *(const float4*)(xsp + t);
    float4 Bq = __ldg((const float4*)(Bp + t));
    float4 Cq = __ldg((const float4*)(Cp + t));
    float4 zv = make_float4(0,0,0,0);
    if (yl) zv = *(const float4*)(zsp + t);
    float da[4] = {dq.x,dq.y,dq.z,dq.w};
    float ua[4] = {uq.x,uq.y,uq.z,uq.w};
    float Ba[4] = {Bq.x,Bq.y,Bq.z,Bq.w};
    float Ca[4] = {Cq.x,Cq.y,Cq.z,Cq.w};
    float za[4] = {zv.x,zv.y,zv.z,zv.w};
    #pragma unroll
    for (int j = 0; j < 4; j++){
      float a = __expf(da[j]*A);
      h = fmaf(h, a, da[j]*ua[j]*Ba[j]);
      float acc = h * Ca[j];
      acc += __shfl_xor_sync(0xffffffffu, acc, 1);
      acc += __shfl_xor_sync(0xffffffffu, acc, 2);
      acc += __shfl_xor_sync(0xffffffffu, acc, 4);
      acc += __shfl_xor_sync(0xffffffffu, acc, 8);
      if (yl && (t + j > 0))
        yp[(t+j-1)*DIN] = fmaf(ua[j], Dd, acc) * za[j];
    }
  }
  { // tail t = L-1
    int t = L-1;
    float dtv = dtp[t], u = xsp[t];
    float Bv = __ldg(Bp + t), Cv = __ldg(Cp + t);
    float a = __expf(dtv*A);
    h = fmaf(h, a, dtv*u*Bv);
    float acc = h * Cv;
    acc += __shfl_xor_sync(0xffffffffu, acc, 1);
    acc += __shfl_xor_sync(0xffffffffu, acc, 2);
    acc += __shfl_xor_sync(0xffffffffu, acc, 4);
    acc += __shfl_xor_sync(0xffffffffu, acc, 8);
    if (yl) yp[(t-1)*DIN] = fmaf(u, Dd, acc) * zsp[t];
  }
}

__global__ void __launch_bounds__(256) k_scan(
  const float* __restrict__ alogA, const float* __restrict__ DA,
  const float* __restrict__ alogB, const float* __restrict__ DB)
{
  int wg = (blockIdx.x*256 + threadIdx.x) >> 5;   // 0..5119
  int lane = threadIdx.x & 31;
  if (wg < 2048){
    int n = wg >> 5, ch2 = (wg & 31)*2;
    scan_seq<LA,64,LPA>(gA_dtT, gA_xsT, gA_zsT, gA_bcT, gA_y, alogA, DA, n, ch2, lane);
  } else {
    int w2 = wg - 2048;
    if (w2 < 1536){
      int n = w2/24, ch2 = (w2 - n*24)*2;
      scan_seq<LB,48,LPB>(gB_dtT0, gB_xsT0, gB_zsT0, gB_bcT0, gB_y0, alogB, DB, n, ch2, lane);
    } else {
      w2 -= 1536;
      int n = w2/24, ch2 = (w2 - n*24)*2;
      scan_seq<LB,48,LPB>(gB_dtT1, gB_xsT1, gB_zsT1, gB_bcT1, gB_y1, alogB, DB, n, ch2, lane);
    }
  }
}

// ============ K4: out_proj ============
template<int RUN>
__global__ void __launch_bounds__(128) k_outproj(const float* __restrict__ Wo)
{
  constexpr int DIN = (RUN==0)?64:48;
  constexpr int DM  = (RUN==0)?32:24;
  constexpr int LT  = ((RUN==0)?LA:LB) - 1;
  int zz = (RUN==0)?0:blockIdx.z;
  const float* y = (RUN==0) ? gA_y : (zz==0 ? gB_y0 : gB_y1);
  float* o       = (RUN==0) ? gA_o : (zz==0 ? gB_o0 : gB_o1);
  __shared__ float Wt[DIN*32];
  __shared__ __align__(16) float vsh[4][DIN][8];
  int tid = threadIdx.x;
  for (int i = tid; i < DIN*32; i += 128){
    int d = i >> 5, oo = i & 31;
    Wt[i] = (oo < DM) ? Wo[oo*DIN + d] : 0.f;
  }
  int w = tid >> 5, lane = tid & 31;
  int n = blockIdx.y;
  int t0 = (blockIdx.x*4 + w)*8;
  #pragma unroll
  for (int tok = 0; tok < 8; tok++){
    int t = t0 + tok; if (t > LT-1) t = LT-1;
    const float* ypt = y + (size_t)(n*LT + t)*DIN;
    vsh[w][lane][tok] = ypt[lane];
    if (DIN > 32 && lane < DIN-32) vsh[w][32+lane][tok] = ypt[32+lane];
  }
  __syncthreads();
  float acc[8] = {0,0,0,0,0,0,0,0};
  #pragma unroll 4
  for (int d = 0; d < DIN; d++){
    float wv = Wt[d*32 + lane];
    float4 v0 = ((const float4*)vsh[w][d])[0];
    float4 v1 = ((const float4*)vsh[w][d])[1];
    acc[0] = fmaf(wv, v0.x, acc[0]);
    acc[1] = fmaf(wv, v0.y, acc[1]);
    acc[2] = fmaf(wv, v0.z, acc[2]);
    acc[3] = fmaf(wv, v0.w, acc[3]);
    acc[4] = fmaf(wv, v1.x, acc[4]);
    acc[5] = fmaf(wv, v1.y, acc[5]);
    acc[6] = fmaf(wv, v1.z, acc[6]);
    acc[7] = fmaf(wv, v1.w, acc[7]);
  }
  if (lane < DM){
    #pragma unroll
    for (int tok = 0; tok < 8; tok++){
      int t = t0 + tok;
      if (t < LT) o[(size_t)(n*LT + t)*DM + lane] = acc[tok];
    }
  }
}

// ============ K5: combine into output ============
__global__ void __launch_bounds__(256) k_combine(float* __restrict__ out)
{
  int idx = blockIdx.x*256 + threadIdx.x;
  if (idx >= 128*192*192) return;
  int c = idx / 36864;
  int rem = idx - c*36864;
  int n = rem / 576;
  int rem2 = rem - n*576;
  int i = rem2 / 24;
  int j = rem2 - i*24;
  int d = c >> 2, r1 = (c >> 1) & 1, r2 = c & 1;
  float v0 = gA_o [(size_t)(n*2304 + (2*i+r1)*48 + 2*j + r2)*32 + d];
  float v1 = gB_o0[(size_t)(n*3072 + c*24 + j)*24 + i];
  float v2 = gB_o1[(size_t)(n*3072 + c*24 + i)*24 + j];
  out[idx] = (v0 + v1 + v2) * (1.f/3.f);
}

// ============ host launch ============
extern "C" void kernel_launch(void* const* d_in, const int* in_sizes, int n_in,
                              void* d_out, int out_size) {
  (void)in_sizes; (void)n_in; (void)out_size;
  const float* X   = (const float*)d_in[0];
  const float* NW  = (const float*)d_in[1];
  const float* NB  = (const float*)d_in[2];
  const float* N2W = (const float*)d_in[3];
  const float* N2B = (const float*)d_in[4];
  const float* GT1 = (const float*)d_in[5];
  const float* GT2 = (const float*)d_in[6];
  const float* M1_IN  = (const float*)d_in[7];
  const float* M1_CW  = (const float*)d_in[8];
  const float* M1_CB  = (const float*)d_in[9];
  const float* M1_XW  = (const float*)d_in[10];
  const float* M1_DTW = (const float*)d_in[11];
  const float* M1_DTB = (const float*)d_in[12];
  const float* M1_AL  = (const float*)d_in[13];
  const float* M1_D   = (const float*)d_in[14];
  const float* M1_OW  = (const float*)d_in[15];
  const float* M2_IN  = (const float*)d_in[16];
  const float* M2_CW  = (const float*)d_in[17];
  const float* M2_CB  = (const float*)d_in[18];
  const float* M2_XW  = (const float*)d_in[19];
  const float* M2_DTW = (const float*)d_in[20];
  const float* M2_DTB = (const float*)d_in[21];
  const float* M2_AL  = (const float*)d_in[22];
  const float* M2_D   = (const float*)d_in[23];
  const float* M2_OW  = (const float*)d_in[24];

  k_inproj<0><<<dim3((LA+31)/32, 64, 1), 128>>>(X, NW,  NB,  GT1, M1_IN);
  k_inproj<1><<<dim3((LB+31)/32, 64, 2), 128>>>(X, N2W, N2B, GT2, M2_IN);

  k_convxp<0><<<dim3((LA+31)/32, 64, 1), 256>>>(M1_CW, M1_CB, M1_XW, M1_DTW, M1_DTB);
  k_convxp<1><<<dim3((LB+31)/32, 64, 2), 256>>>(M2_CW, M2_CB, M2_XW, M2_DTW, M2_DTB);

  k_scan<<<640, 256>>>(M1_AL, M1_D, M2_AL, M2_D);

  k_outproj<0><<<dim3(72, 64, 1), 128>>>(M1_OW);
  k_outproj<1><<<dim3(96, 64, 2), 128>>>(M2_OW);

  k_combine<<<18432, 256>>>((float*)d_out);
}

// round 5
// speedup vs baseline: 1.5036x; 1.5036x over previous
#include <cuda_runtime.h>
#include <math.h>

#define NSEQ 64
static constexpr int LA  = 2305;   // run0 length (1 gt + 48*48)
static constexpr int LB  = 3073;   // run1/2 length (1 gt + 128*24)
static constexpr int LPA = 2336;   // padded strides (mult of 32)
static constexpr int LPB = 3104;
static constexpr int LTA = 2304;   // output token counts (mult of 32)
static constexpr int LTB = 3072;

// ---------- scratch (device globals; allocation-free) ----------
__device__ __align__(16) float gA_xz [NSEQ*LA*128];
__device__ __align__(16) float gA_dtT[NSEQ*64*LPA];
__device__ __align__(16) float gA_xsT[NSEQ*64*LPA];
__device__ __align__(16) float gA_zsT[NSEQ*64*LPA];
__device__ __align__(16) float gA_bcI[NSEQ*32*LPA];   // [n][tb][comp32][4]
__device__ __align__(16) float gA_yT [NSEQ*64*LTA];   // [n][ch][t]
__device__ __align__(16) float gA_o  [NSEQ*LTA*32];

__device__ __align__(16) float gB_xz0 [NSEQ*LB*96];
__device__ __align__(16) float gB_dtT0[NSEQ*48*LPB];
__device__ __align__(16) float gB_xsT0[NSEQ*48*LPB];
__device__ __align__(16) float gB_zsT0[NSEQ*48*LPB];
__device__ __align__(16) float gB_bcI0[NSEQ*32*LPB];
__device__ __align__(16) float gB_yT0 [NSEQ*48*LTB];
__device__ __align__(16) float gB_o0  [NSEQ*LTB*24];

__device__ __align__(16) float gB_xz1 [NSEQ*LB*96];
__device__ __align__(16) float gB_dtT1[NSEQ*48*LPB];
__device__ __align__(16) float gB_xsT1[NSEQ*48*LPB];
__device__ __align__(16) float gB_zsT1[NSEQ*48*LPB];
__device__ __align__(16) float gB_bcI1[NSEQ*32*LPB];
__device__ __align__(16) float gB_yT1 [NSEQ*48*LTB];
__device__ __align__(16) float gB_o1  [NSEQ*LTB*24];

template<int RUN> __device__ __forceinline__ float* bufXZ(){
  if constexpr (RUN==0) return gA_xz; else if constexpr (RUN==1) return gB_xz0; else return gB_xz1; }
template<int RUN> __device__ __forceinline__ float* bufDTT(){
  if constexpr (RUN==0) return gA_dtT; else if constexpr (RUN==1) return gB_dtT0; else return gB_dtT1; }
template<int RUN> __device__ __forceinline__ float* bufXST(){
  if constexpr (RUN==0) return gA_xsT; else if constexpr (RUN==1) return gB_xsT0; else return gB_xsT1; }
template<int RUN> __device__ __forceinline__ float* bufZST(){
  if constexpr (RUN==0) return gA_zsT; else if constexpr (RUN==1) return gB_zsT0; else return gB_zsT1; }
template<int RUN> __device__ __forceinline__ float* bufBCI(){
  if constexpr (RUN==0) return gA_bcI; else if constexpr (RUN==1) return gB_bcI0; else return gB_bcI1; }
template<int RUN> __device__ __forceinline__ float* bufYT(){
  if constexpr (RUN==0) return gA_yT; else if constexpr (RUN==1) return gB_yT0; else return gB_yT1; }
template<int RUN> __device__ __forceinline__ float* bufO(){
  if constexpr (RUN==0) return gA_o; else if constexpr (RUN==1) return gB_o0; else return gB_o1; }

__device__ __forceinline__ float warp_sum(float v){
  v += __shfl_xor_sync(0xffffffffu, v, 16);
  v += __shfl_xor_sync(0xffffffffu, v, 8);
  v += __shfl_xor_sync(0xffffffffu, v, 4);
  v += __shfl_xor_sync(0xffffffffu, v, 2);
  v += __shfl_xor_sync(0xffffffffu, v, 1);
  return v;
}
__device__ __forceinline__ float silu_f(float x){
  return __fdividef(x, 1.f + __expf(-x));
}

// ============ K1: gather + layernorm + in_proj ============
template<int RUN>
__global__ void __launch_bounds__(128) k_inproj(
    const float* __restrict__ x, const float* __restrict__ nw,
    const float* __restrict__ nb, const float* __restrict__ gt,
    const float* __restrict__ Win)
{
  constexpr int DM  = (RUN==0)?32:24;
  constexpr int DXZ = (RUN==0)?128:96;
  constexpr int LF  = (RUN==0)?LA:LB;
  constexpr int KO  = DXZ/32;
  __shared__ float Wt[DM*DXZ];                    // [d][o]
  __shared__ __align__(16) float vsh[4][DM][8];

  int tid = threadIdx.x;
  for (int i = tid; i < DXZ*DM; i += 128){
    int o = i / DM, d = i - o*DM;
    Wt[d*DXZ + o] = Win[i];
  }
  int w = tid >> 5, lane = tid & 31;
  int n = blockIdx.y, bh = n >> 3, bw = n & 7;
  int t0 = (blockIdx.x*4 + w)*8;

  float v[8];
  #pragma unroll
  for (int tok = 0; tok < 8; tok++){
    int t = t0 + tok; float val = 0.f;
    if (lane < DM && t < LF){
      if (t == 0) val = gt[lane];
      else {
        int q = t - 1, addr;
        if (RUN == 0){
          int row = q / 48, col = q - row*48;
          int i0 = row >> 1, r1 = row & 1, j0 = col >> 1, r2 = col & 1;
          addr = (lane*4 + r1*2 + r2)*36864 + (bh*24 + i0)*192 + bw*24 + j0;
        } else if (RUN == 1){
          int c = q / 24, p = q - c*24;
          addr = c*36864 + (bh*24 + lane)*192 + bw*24 + p;
        } else {
          int c = q / 24, p = q - c*24;
          addr = c*36864 + (bh*24 + p)*192 + bw*24 + lane;
        }
        val = __ldg(x + addr);
      }
    }
    v[tok] = val;
  }
  float nwv = (lane < DM) ? nw[lane] : 0.f;
  float nbv = (lane < DM) ? nb[lane] : 0.f;
  #pragma unroll
  for (int tok = 0; tok < 8; tok++){
    float s  = warp_sum(v[tok]);
    float s2 = warp_sum(v[tok]*v[tok]);
    float m  = s * (1.f/DM);
    float var = s2 * (1.f/DM) - m*m;
    float vn = (v[tok] - m) * rsqrtf(var + 1e-5f) * nwv + nbv;
    if (lane < DM) vsh[w][lane][tok] = vn;
  }
  __syncthreads();

  float acc[KO][8];
  #pragma unroll
  for (int k = 0; k < KO; k++)
    #pragma unroll
    for (int j = 0; j < 8; j++) acc[k][j] = 0.f;

  #pragma unroll 4
  for (int d = 0; d < DM; d++){
    float4 v0 = ((const float4*)vsh[w][d])[0];
    float4 v1 = ((const float4*)vsh[w][d])[1];
    #pragma unroll
    for (int k = 0; k < KO; k++){
      float wv = Wt[d*DXZ + lane + 32*k];
      acc[k][0] = fmaf(wv, v0.x, acc[k][0]);
      acc[k][1] = fmaf(wv, v0.y, acc[k][1]);
      acc[k][2] = fmaf(wv, v0.z, acc[k][2]);
      acc[k][3] = fmaf(wv, v0.w, acc[k][3]);
      acc[k][4] = fmaf(wv, v1.x, acc[k][4]);
      acc[k][5] = fmaf(wv, v1.y, acc[k][5]);
      acc[k][6] = fmaf(wv, v1.z, acc[k][6]);
      acc[k][7] = fmaf(wv, v1.w, acc[k][7]);
    }
  }
  float* xz = bufXZ<RUN>();
  #pragma unroll
  for (int tok = 0; tok < 8; tok++){
    int t = t0 + tok;
    if (t < LF){
      float* op = xz + (n*LF + t)*DXZ + lane;
      #pragma unroll
      for (int k = 0; k < KO; k++) op[32*k] = acc[k][tok];
    }
  }
}

// ============ K2: conv + silu + x_proj + dt ; smem staged, coalesced flush ============
template<int RUN>
__global__ void __launch_bounds__(256) k_convxp(
  const float* __restrict__ convw, const float* __restrict__ convb,
  const float* __restrict__ Wx,    const float* __restrict__ dtw,
  const float* __restrict__ dtb)
{
  constexpr int DIN = (RUN==0)?64:48;
  constexpr int DXZ = 2*DIN;
  constexpr int LF  = (RUN==0)?LA:LB;
  constexpr int LFP = (RUN==0)?LPA:LPB;
  const float* xz = bufXZ<RUN>();
  float* xsT = bufXST<RUN>();
  float* zsT = bufZST<RUN>();
  float* dtT = bufDTT<RUN>();
  float* bcI = bufBCI<RUN>();

  __shared__ float Wxt[DIN*34];        // [d][o]
  __shared__ float xs_s[DIN][33];
  __shared__ float zs_s[DIN][33];
  __shared__ float dt_s[DIN][33];
  __shared__ float bc_s[32][33];

  int tid = threadIdx.x;
  for (int i = tid; i < 34*DIN; i += 256){
    int o = i / DIN, d = i - o*DIN;
    Wxt[d*34 + o] = Wx[i];
  }
  int w = tid >> 5, lane = tid & 31;
  int n = blockIdx.y;
  int tile0 = blockIdx.x*32;
  int t0 = tile0 + w*4;

  float cw[2][4], cb[2], w0c[2], w1c[2], db[2];
  #pragma unroll
  for (int kk = 0; kk < 2; kk++){
    int ch = lane + 32*kk;
    bool ok = ch < DIN;
    #pragma unroll
    for (int k = 0; k < 4; k++) cw[kk][k] = ok ? convw[ch*4+k] : 0.f;
    cb[kk]  = ok ? convb[ch]   : 0.f;
    w0c[kk] = ok ? dtw[ch*2+0] : 0.f;
    w1c[kk] = ok ? dtw[ch*2+1] : 0.f;
    db[kk]  = ok ? dtb[ch]     : 0.f;
  }
  #pragma unroll
  for (int tok = 0; tok < 4; tok++){
    int t = t0 + tok;
    bool valid = t < LF;
    #pragma unroll
    for (int kk = 0; kk < 2; kk++){
      int ch = lane + 32*kk;
      if (ch < DIN){
        float a = cb[kk];
        float zval = 0.f;
        if (valid){
          #pragma unroll
          for (int k = 0; k < 4; k++){
            int ts = t + k - 3;
            if (ts >= 0) a = fmaf(xz[(n*LF + ts)*DXZ + ch], cw[kk][k], a);
          }
          zval = xz[(n*LF + t)*DXZ + DIN + ch];
        }
        xs_s[ch][w*4+tok] = silu_f(a);
        zs_s[ch][w*4+tok] = silu_f(zval);
      }
    }
  }
  __syncthreads();   // Wxt + xs_s ready

  float acc[4]  = {0,0,0,0};
  float acc2[4] = {0,0,0,0};
  #pragma unroll 8
  for (int d = 0; d < DIN; d++){
    float wv = Wxt[d*34 + lane];
    float x0 = xs_s[d][w*4+0];
    float x1 = xs_s[d][w*4+1];
    float x2 = xs_s[d][w*4+2];
    float x3 = xs_s[d][w*4+3];
    acc[0] = fmaf(wv, x0, acc[0]);
    acc[1] = fmaf(wv, x1, acc[1]);
    acc[2] = fmaf(wv, x2, acc[2]);
    acc[3] = fmaf(wv, x3, acc[3]);
    if (lane < 2){
      float w2 = Wxt[d*34 + 32 + lane];
      acc2[0] = fmaf(w2, x0, acc2[0]);
      acc2[1] = fmaf(w2, x1, acc2[1]);
      acc2[2] = fmaf(w2, x2, acc2[2]);
      acc2[3] = fmaf(w2, x3, acc2[3]);
    }
  }
  #pragma unroll
  for (int tok = 0; tok < 4; tok++){
    float d0 = __shfl_sync(0xffffffffu, acc[tok], 0);
    float d1 = __shfl_sync(0xffffffffu, acc[tok], 1);
    #pragma unroll
    for (int kk = 0; kk < 2; kk++){
      int ch = lane + 32*kk;
      if (ch < DIN){
        float r = fmaf(w0c[kk], d0, fmaf(w1c[kk], d1, db[kk]));
        dt_s[ch][w*4+tok] = fmaxf(r, 0.f) + __logf(1.f + __expf(-fabsf(r)));
      }
    }
    if (lane >= 2) bc_s[lane-2][w*4+tok]  = acc[tok];
    else           bc_s[30+lane][w*4+tok] = acc2[tok];
  }
  __syncthreads();

  // coalesced flush: consecutive threads -> consecutive float4 along t
  for (int i = tid; i < DIN*8; i += 256){
    int ch = i >> 3, v = i & 7;
    int tt = tile0 + 4*v;
    size_t off = (size_t)(n*DIN + ch)*LFP + tt;
    *(float4*)(xsT + off) = make_float4(xs_s[ch][4*v],xs_s[ch][4*v+1],xs_s[ch][4*v+2],xs_s[ch][4*v+3]);
    *(float4*)(zsT + off) = make_float4(zs_s[ch][4*v],zs_s[ch][4*v+1],zs_s[ch][4*v+2],zs_s[ch][4*v+3]);
    *(float4*)(dtT + off) = make_float4(dt_s[ch][4*v],dt_s[ch][4*v+1],dt_s[ch][4*v+2],dt_s[ch][4*v+3]);
  }
  // bc interleaved flush: [n][tb][comp][4]; one float4 per thread (8 tb x 32 comp)
  {
    int tbl = tid >> 5, comp = tid & 31;
    float4 bv = make_float4(bc_s[comp][4*tbl],bc_s[comp][4*tbl+1],bc_s[comp][4*tbl+2],bc_s[comp][4*tbl+3]);
    *(float4*)(bcI + ((size_t)(n*(LFP/4) + tile0/4 + tbl)*32 + comp)*4) = bv;
  }
}

// ============ K3: selective scan (coalesced B/C, buffered y stores) ============
template<int L, int DIN, int LFP, int LT>
__device__ __forceinline__ void scan_seq(
  const float* __restrict__ dtT, const float* __restrict__ xsT,
  const float* __restrict__ zsT, const float* __restrict__ bcI,
  float* __restrict__ yT, const float* __restrict__ alog,
  const float* __restrict__ Dv, int n, int ch2, int lane)
{
  int half = lane >> 4, s = lane & 15;
  int ch = ch2 + half;
  const float* dtp = dtT + (size_t)(n*DIN + ch)*LFP;
  const float* xsp = xsT + (size_t)(n*DIN + ch)*LFP;
  const float* zsp = zsT + (size_t)(n*DIN + ch)*LFP;
  const float* bcn = bcI + (size_t)n*(LFP/4)*128;
  float A  = -expf(__ldg(alog + ch*16 + s));
  float Dd = __ldg(Dv + ch);
  float* yTp = yT + (size_t)(n*DIN + ch)*LT;
  bool yl = (s == 0);
  float h = 0.f;
  float yb0=0.f, yb1=0.f, yb2=0.f;
  constexpr int NB = (L-1)/4;
  for (int tb = 0; tb < NB; tb++){
    int t = tb*4;
    float4 dq = __ldg((const float4*)(dtp + t));
    float4 uq = __ldg((const float4*)(xsp + t));
    float4 Bq = __ldg((const float4*)(bcn + tb*128 + s*4));
    float4 Cq = __ldg((const float4*)(bcn + tb*128 + 64 + s*4));
    float4 zv = make_float4(0,0,0,0);
    if (yl) zv = __ldg((const float4*)(zsp + t));
    float da[4] = {dq.x,dq.y,dq.z,dq.w};
    float ua[4] = {uq.x,uq.y,uq.z,uq.w};
    float Ba[4] = {Bq.x,Bq.y,Bq.z,Bq.w};
    float Ca[4] = {Cq.x,Cq.y,Cq.z,Cq.w};
    float za[4] = {zv.x,zv.y,zv.z,zv.w};
    #pragma unroll
    for (int j = 0; j < 4; j++){
      float a = __expf(da[j]*A);
      h = fmaf(h, a, da[j]*ua[j]*Ba[j]);
      float acc = h * Ca[j];
      acc += __shfl_xor_sync(0xffffffffu, acc, 1);
      acc += __shfl_xor_sync(0xffffffffu, acc, 2);
      acc += __shfl_xor_sync(0xffffffffu, acc, 4);
      acc += __shfl_xor_sync(0xffffffffu, acc, 8);
      if (yl){
        float val = fmaf(ua[j], Dd, acc) * za[j];
        // output index tt = t+j-1 ; flush float4 when tt%4==3 (i.e. j==0, tb>=1)
        if (j == 0){
          if (tb > 0) *(float4*)(yTp + t - 4) = make_float4(yb0, yb1, yb2, val);
        } else if (j == 1) yb0 = val;
        else if (j == 2)   yb1 = val;
        else               yb2 = val;
      }
    }
  }
  { // tail t = L-1 (tt = L-2, slot 3)
    constexpr int t = L-1;
    float dtv = __ldg(dtp + t), u = __ldg(xsp + t);
    float Bv = __ldg(bcn + NB*128 + s*4);
    float Cv = __ldg(bcn + NB*128 + 64 + s*4);
    float a = __expf(dtv*A);
    h = fmaf(h, a, dtv*u*Bv);
    float acc = h * Cv;
    acc += __shfl_xor_sync(0xffffffffu, acc, 1);
    acc += __shfl_xor_sync(0xffffffffu, acc, 2);
    acc += __shfl_xor_sync(0xffffffffu, acc, 4);
    acc += __shfl_xor_sync(0xffffffffu, acc, 8);
    if (yl){
      float val = fmaf(u, Dd, acc) * __ldg(zsp + t);
      *(float4*)(yTp + L - 5) = make_float4(yb0, yb1, yb2, val);
    }
  }
}

__global__ void __launch_bounds__(256) k_scan(
  const float* __restrict__ alogA, const float* __restrict__ DA,
  const float* __restrict__ alogB, const float* __restrict__ DB)
{
  int wg = (blockIdx.x*256 + threadIdx.x) >> 5;   // 0..5119
  int lane = threadIdx.x & 31;
  if (wg < 2048){
    int n = wg >> 5, ch2 = (wg & 31)*2;
    scan_seq<LA,64,LPA,LTA>(gA_dtT, gA_xsT, gA_zsT, gA_bcI, gA_yT, alogA, DA, n, ch2, lane);
  } else {
    int w2 = wg - 2048;
    if (w2 < 1536){
      int n = w2/24, ch2 = (w2 - n*24)*2;
      scan_seq<LB,48,LPB,LTB>(gB_dtT0, gB_xsT0, gB_zsT0, gB_bcI0, gB_yT0, alogB, DB, n, ch2, lane);
    } else {
      w2 -= 1536;
      int n = w2/24, ch2 = (w2 - n*24)*2;
      scan_seq<LB,48,LPB,LTB>(gB_dtT1, gB_xsT1, gB_zsT1, gB_bcI1, gB_yT1, alogB, DB, n, ch2, lane);
    }
  }
}

// ============ K4: out_proj (reads transposed y via smem tile) ============
template<int RUN>
__global__ void __launch_bounds__(256) k_outproj(const float* __restrict__ Wo)
{
  constexpr int DIN = (RUN==0)?64:48;
  constexpr int DM  = (RUN==0)?32:24;
  constexpr int LT  = (RUN==0)?LTA:LTB;
  const float* yT = bufYT<RUN>();
  float* o = bufO<RUN>();
  __shared__ float Wt[DIN*32];
  __shared__ float y_s[DIN][33];
  int tid = threadIdx.x;
  for (int i = tid; i < DIN*32; i += 256){
    int d = i >> 5, oo = i & 31;
    Wt[i] = (oo < DM) ? Wo[oo*DIN + d] : 0.f;
  }
  int w = tid >> 5, lane = tid & 31;
  int n = blockIdx.y;
  int tile0 = blockIdx.x*32;
  for (int i = tid; i < DIN*8; i += 256){
    int ch = i >> 3, v = i & 7;
    float4 yv = *(const float4*)(yT + (size_t)(n*DIN + ch)*LT + tile0 + 4*v);
    y_s[ch][4*v+0] = yv.x; y_s[ch][4*v+1] = yv.y;
    y_s[ch][4*v+2] = yv.z; y_s[ch][4*v+3] = yv.w;
  }
  __syncthreads();
  float acc[4] = {0,0,0,0};
  #pragma unroll 8
  for (int d = 0; d < DIN; d++){
    float wv = Wt[d*32 + lane];
    acc[0] = fmaf(wv, y_s[d][w*4+0], acc[0]);
    acc[1] = fmaf(wv, y_s[d][w*4+1], acc[1]);
    acc[2] = fmaf(wv, y_s[d][w*4+2], acc[2]);
    acc[3] = fmaf(wv, y_s[d][w*4+3], acc[3]);
  }
  if (lane < DM){
    #pragma unroll
    for (int tok = 0; tok < 4; tok++){
      int t = tile0 + w*4 + tok;
      o[(size_t)(n*LT + t)*DM + lane] = acc[tok];
    }
  }
}

// ============ K5: combine into output ============
__global__ void __launch_bounds__(256) k_combine(float* __restrict__ out)
{
  int idx = blockIdx.x*256 + threadIdx.x;
  if (idx >= 128*192*192) return;
  int c = idx / 36864;
  int rem = idx - c*36864;
  int n = rem / 576;
  int rem2 = rem - n*576;
  int i = rem2 / 24;
  int j = rem2 - i*24;
  int d = c >> 2, r1 = (c >> 1) & 1, r2 = c & 1;
  float v0 = gA_o [(size_t)(n*2304 + (2*i+r1)*48 + 2*j + r2)*32 + d];
  float v1 = gB_o0[(size_t)(n*3072 + c*24 + j)*24 + i];
  float v2 = gB_o1[(size_t)(n*3072 + c*24 + i)*24 + j];
  out[idx] = (v0 + v1 + v2) * (1.f/3.f);
}

// ============ host launch ============
extern "C" void kernel_launch(void* const* d_in, const int* in_sizes, int n_in,
                              void* d_out, int out_size) {
  (void)in_sizes; (void)n_in; (void)out_size;
  const float* X   = (const float*)d_in[0];
  const float* NW  = (const float*)d_in[1];
  const float* NB  = (const float*)d_in[2];
  const float* N2W = (const float*)d_in[3];
  const float* N2B = (const float*)d_in[4];
  const float* GT1 = (const float*)d_in[5];
  const float* GT2 = (const float*)d_in[6];
  const float* M1_IN  = (const float*)d_in[7];
  const float* M1_CW  = (const float*)d_in[8];
  const float* M1_CB  = (const float*)d_in[9];
  const float* M1_XW  = (const float*)d_in[10];
  const float* M1_DTW = (const float*)d_in[11];
  const float* M1_DTB = (const float*)d_in[12];
  const float* M1_AL  = (const float*)d_in[13];
  const float* M1_D   = (const float*)d_in[14];
  const float* M1_OW  = (const float*)d_in[15];
  const float* M2_IN  = (const float*)d_in[16];
  const float* M2_CW  = (const float*)d_in[17];
  const float* M2_CB  = (const float*)d_in[18];
  const float* M2_XW  = (const float*)d_in[19];
  const float* M2_DTW = (const float*)d_in[20];
  const float* M2_DTB = (const float*)d_in[21];
  const float* M2_AL  = (const float*)d_in[22];
  const float* M2_D   = (const float*)d_in[23];
  const float* M2_OW  = (const float*)d_in[24];

  k_inproj<0><<<dim3(73, 64), 128>>>(X, NW,  NB,  GT1, M1_IN);
  k_inproj<1><<<dim3(97, 64), 128>>>(X, N2W, N2B, GT2, M2_IN);
  k_inproj<2><<<dim3(97, 64), 128>>>(X, N2W, N2B, GT2, M2_IN);

  k_convxp<0><<<dim3(73, 64), 256>>>(M1_CW, M1_CB, M1_XW, M1_DTW, M1_DTB);
  k_convxp<1><<<dim3(97, 64), 256>>>(M2_CW, M2_CB, M2_XW, M2_DTW, M2_DTB);
  k_convxp<2><<<dim3(97, 64), 256>>>(M2_CW, M2_CB, M2_XW, M2_DTW, M2_DTB);

  k_scan<<<640, 256>>>(M1_AL, M1_D, M2_AL, M2_D);

  k_outproj<0><<<dim3(72, 64), 256>>>(M1_OW);
  k_outproj<1><<<dim3(96, 64), 256>>>(M2_OW);
  k_outproj<2><<<dim3(96, 64), 256>>>(M2_OW);

  k_combine<<<18432, 256>>>((float*)d_out);
}

// round 6
// speedup vs baseline: 1.5611x; 1.0383x over previous
#include <cuda_runtime.h>
#include <math.h>

#define NSEQ 64
static constexpr int LA  = 2305;   // run0 length (1 gt + 48*48)
static constexpr int LB  = 3073;   // run1/2 length (1 gt + 128*24)
static constexpr int LPA = 2336;   // padded strides (mult of 32)
static constexpr int LPB = 3104;
static constexpr int LTA = 2304;   // output token counts (mult of 32)
static constexpr int LTB = 3072;

// ---------- scratch (device globals; allocation-free) ----------
__device__ __align__(16) float gA_xz [NSEQ*LA*128];
__device__ __align__(16) float gA_dtT[NSEQ*64*LPA];
__device__ __align__(16) float gA_xsT[NSEQ*64*LPA];
__device__ __align__(16) float gA_zsT[NSEQ*64*LPA];
__device__ __align__(16) float gA_bcI[NSEQ*32*LPA];   // [n][tb][comp32][4]
__device__ __align__(16) float gA_yT [NSEQ*64*LTA];   // [n][ch][t]
__device__ __align__(16) float gA_o  [NSEQ*LTA*32];

__device__ __align__(16) float gB_xz0 [NSEQ*LB*96];
__device__ __align__(16) float gB_dtT0[NSEQ*48*LPB];
__device__ __align__(16) float gB_xsT0[NSEQ*48*LPB];
__device__ __align__(16) float gB_zsT0[NSEQ*48*LPB];
__device__ __align__(16) float gB_bcI0[NSEQ*32*LPB];
__device__ __align__(16) float gB_yT0 [NSEQ*48*LTB];
__device__ __align__(16) float gB_o0  [NSEQ*LTB*24];

__device__ __align__(16) float gB_xz1 [NSEQ*LB*96];
__device__ __align__(16) float gB_dtT1[NSEQ*48*LPB];
__device__ __align__(16) float gB_xsT1[NSEQ*48*LPB];
__device__ __align__(16) float gB_zsT1[NSEQ*48*LPB];
__device__ __align__(16) float gB_bcI1[NSEQ*32*LPB];
__device__ __align__(16) float gB_yT1 [NSEQ*48*LTB];
__device__ __align__(16) float gB_o1  [NSEQ*LTB*24];

template<int RUN> __device__ __forceinline__ float* bufXZ(){
  if constexpr (RUN==0) return gA_xz; else if constexpr (RUN==1) return gB_xz0; else return gB_xz1; }
template<int RUN> __device__ __forceinline__ float* bufDTT(){
  if constexpr (RUN==0) return gA_dtT; else if constexpr (RUN==1) return gB_dtT0; else return gB_dtT1; }
template<int RUN> __device__ __forceinline__ float* bufXST(){
  if constexpr (RUN==0) return gA_xsT; else if constexpr (RUN==1) return gB_xsT0; else return gB_xsT1; }
template<int RUN> __device__ __forceinline__ float* bufZST(){
  if constexpr (RUN==0) return gA_zsT; else if constexpr (RUN==1) return gB_zsT0; else return gB_zsT1; }
template<int RUN> __device__ __forceinline__ float* bufBCI(){
  if constexpr (RUN==0) return gA_bcI; else if constexpr (RUN==1) return gB_bcI0; else return gB_bcI1; }
template<int RUN> __device__ __forceinline__ float* bufYT(){
  if constexpr (RUN==0) return gA_yT; else if constexpr (RUN==1) return gB_yT0; else return gB_yT1; }
template<int RUN> __device__ __forceinline__ float* bufO(){
  if constexpr (RUN==0) return gA_o; else if constexpr (RUN==1) return gB_o0; else return gB_o1; }

__device__ __forceinline__ float warp_sum(float v){
  v += __shfl_xor_sync(0xffffffffu, v, 16);
  v += __shfl_xor_sync(0xffffffffu, v, 8);
  v += __shfl_xor_sync(0xffffffffu, v, 4);
  v += __shfl_xor_sync(0xffffffffu, v, 2);
  v += __shfl_xor_sync(0xffffffffu, v, 1);
  return v;
}
__device__ __forceinline__ float silu_f(float x){
  return __fdividef(x, 1.f + __expf(-x));
}

// ---------- packed f32x2 helpers ----------
__device__ __forceinline__ unsigned long long pack2(float lo, float hi){
  unsigned long long r;
  asm("mov.b64 %0, {%1, %2};" : "=l"(r) : "f"(lo), "f"(hi));
  return r;
}
__device__ __forceinline__ float2 unpack2(unsigned long long v){
  float2 f;
  asm("mov.b64 {%0, %1}, %2;" : "=f"(f.x), "=f"(f.y) : "l"(v));
  return f;
}
__device__ __forceinline__ void ffma2(unsigned long long &d, unsigned long long a, unsigned long long b){
  asm("fma.rn.f32x2 %0, %1, %2, %0;" : "+l"(d) : "l"(a), "l"(b));
}

// ============ K1: gather + layernorm + in_proj (FFMA2) ============
template<int RUN>
__global__ void __launch_bounds__(128) k_inproj(
    const float* __restrict__ x, const float* __restrict__ nw,
    const float* __restrict__ nb, const float* __restrict__ gt,
    const float* __restrict__ Win)
{
  constexpr int DM  = (RUN==0)?32:24;
  constexpr int DXZ = (RUN==0)?128:96;
  constexpr int LF  = (RUN==0)?LA:LB;
  constexpr int KO  = DXZ/32;
  __shared__ float Wtr[DM*128];                   // [d][lane][4] (k padded to 4)
  __shared__ __align__(16) float vsh[4][DM][8];

  int tid = threadIdx.x;
  for (int i = tid; i < DM*128; i += 128){
    int d = i >> 7, r = i & 127, ln = r >> 2, k = r & 3;
    Wtr[i] = (k < KO) ? Win[(k*32+ln)*DM + d] : 0.f;
  }
  int w = tid >> 5, lane = tid & 31;
  int n = blockIdx.y, bh = n >> 3, bw = n & 7;
  int t0 = (blockIdx.x*4 + w)*8;

  float v[8];
  #pragma unroll
  for (int tok = 0; tok < 8; tok++){
    int t = t0 + tok; float val = 0.f;
    if (lane < DM && t < LF){
      if (t == 0) val = gt[lane];
      else {
        int q = t - 1, addr;
        if (RUN == 0){
          int row = q / 48, col = q - row*48;
          int i0 = row >> 1, r1 = row & 1, j0 = col >> 1, r2 = col & 1;
          addr = (lane*4 + r1*2 + r2)*36864 + (bh*24 + i0)*192 + bw*24 + j0;
        } else if (RUN == 1){
          int c = q / 24, p = q - c*24;
          addr = c*36864 + (bh*24 + lane)*192 + bw*24 + p;
        } else {
          int c = q / 24, p = q - c*24;
          addr = c*36864 + (bh*24 + p)*192 + bw*24 + lane;
        }
        val = __ldg(x + addr);
      }
    }
    v[tok] = val;
  }
  float nwv = (lane < DM) ? nw[lane] : 0.f;
  float nbv = (lane < DM) ? nb[lane] : 0.f;
  #pragma unroll
  for (int tok = 0; tok < 8; tok++){
    float s  = warp_sum(v[tok]);
    float s2 = warp_sum(v[tok]*v[tok]);
    float m  = s * (1.f/DM);
    float var = s2 * (1.f/DM) - m*m;
    float vn = (v[tok] - m) * rsqrtf(var + 1e-5f) * nwv + nbv;
    if (lane < DM) vsh[w][lane][tok] = vn;
  }
  __syncthreads();

  unsigned long long accp[KO][4];
  #pragma unroll
  for (int k = 0; k < KO; k++)
    #pragma unroll
    for (int p = 0; p < 4; p++) accp[k][p] = 0ull;

  #pragma unroll 4
  for (int d = 0; d < DM; d++){
    const ulonglong2* vp = (const ulonglong2*)vsh[w][d];
    ulonglong2 va = vp[0], vb = vp[1];         // pairs (t0,t1)(t2,t3) / (t4,t5)(t6,t7)
    float4 wq = *(const float4*)&Wtr[(d*32+lane)*4];
    float wa[4] = {wq.x, wq.y, wq.z, wq.w};
    #pragma unroll
    for (int k = 0; k < KO; k++){
      unsigned long long wp = pack2(wa[k], wa[k]);
      ffma2(accp[k][0], wp, va.x);
      ffma2(accp[k][1], wp, va.y);
      ffma2(accp[k][2], wp, vb.x);
      ffma2(accp[k][3], wp, vb.y);
    }
  }
  float* xz = bufXZ<RUN>();
  #pragma unroll
  for (int p = 0; p < 4; p++){
    float2 f[KO];
    #pragma unroll
    for (int k = 0; k < KO; k++) f[k] = unpack2(accp[k][p]);
    #pragma unroll
    for (int e = 0; e < 2; e++){
      int t = t0 + 2*p + e;
      if (t < LF){
        float* op = xz + (n*LF + t)*DXZ + lane;
        #pragma unroll
        for (int k = 0; k < KO; k++) op[32*k] = e ? f[k].y : f[k].x;
      }
    }
  }
}

// ============ K2: conv + silu + x_proj + dt (FFMA2 xproj) ============
template<int RUN>
__global__ void __launch_bounds__(256) k_convxp(
  const float* __restrict__ convw, const float* __restrict__ convb,
  const float* __restrict__ Wx,    const float* __restrict__ dtw,
  const float* __restrict__ dtb)
{
  constexpr int DIN = (RUN==0)?64:48;
  constexpr int DXZ = 2*DIN;
  constexpr int LF  = (RUN==0)?LA:LB;
  constexpr int LFP = (RUN==0)?LPA:LPB;
  const float* xz = bufXZ<RUN>();
  float* xsT = bufXST<RUN>();
  float* zsT = bufZST<RUN>();
  float* dtT = bufDTT<RUN>();
  float* bcI = bufBCI<RUN>();

  __shared__ float Wxt[DIN*34];          // [d][o]
  __shared__ __align__(16) float xs_s[DIN][34];
  __shared__ __align__(16) float zs_s[DIN][34];
  __shared__ __align__(16) float dt_s[DIN][34];
  __shared__ float bc_s[32][33];

  int tid = threadIdx.x;
  for (int i = tid; i < 34*DIN; i += 256){
    int o = i / DIN, d = i - o*DIN;
    Wxt[d*34 + o] = Wx[i];
  }
  int w = tid >> 5, lane = tid & 31;
  int n = blockIdx.y;
  int tile0 = blockIdx.x*32;
  int t0 = tile0 + w*4;

  float cw[2][4], cb[2], w0c[2], w1c[2], db[2];
  #pragma unroll
  for (int kk = 0; kk < 2; kk++){
    int ch = lane + 32*kk;
    bool ok = ch < DIN;
    #pragma unroll
    for (int k = 0; k < 4; k++) cw[kk][k] = ok ? convw[ch*4+k] : 0.f;
    cb[kk]  = ok ? convb[ch]   : 0.f;
    w0c[kk] = ok ? dtw[ch*2+0] : 0.f;
    w1c[kk] = ok ? dtw[ch*2+1] : 0.f;
    db[kk]  = ok ? dtb[ch]     : 0.f;
  }
  #pragma unroll
  for (int tok = 0; tok < 4; tok++){
    int t = t0 + tok;
    bool valid = t < LF;
    #pragma unroll
    for (int kk = 0; kk < 2; kk++){
      int ch = lane + 32*kk;
      if (ch < DIN){
        float a = cb[kk];
        float zval = 0.f;
        if (valid){
          #pragma unroll
          for (int k = 0; k < 4; k++){
            int ts = t + k - 3;
            if (ts >= 0) a = fmaf(xz[(n*LF + ts)*DXZ + ch], cw[kk][k], a);
          }
          zval = xz[(n*LF + t)*DXZ + DIN + ch];
        }
        xs_s[ch][w*4+tok] = silu_f(a);
        zs_s[ch][w*4+tok] = silu_f(zval);
      }
    }
  }
  __syncthreads();   // Wxt + xs_s ready

  unsigned long long ap0=0ull, ap1=0ull, a2p0=0ull, a2p1=0ull;
  #pragma unroll 8
  for (int d = 0; d < DIN; d++){
    const unsigned long long* xp = (const unsigned long long*)&xs_s[d][w*4];
    unsigned long long x01 = xp[0], x23 = xp[1];
    float wv = Wxt[d*34 + lane];
    unsigned long long wp = pack2(wv, wv);
    ffma2(ap0, wp, x01);
    ffma2(ap1, wp, x23);
    if (lane < 2){
      float w2 = Wxt[d*34 + 32 + lane];
      unsigned long long wp2 = pack2(w2, w2);
      ffma2(a2p0, wp2, x01);
      ffma2(a2p1, wp2, x23);
    }
  }
  float2 u0 = unpack2(ap0), u1 = unpack2(ap1);
  float acc[4]  = {u0.x, u0.y, u1.x, u1.y};
  float2 q0 = unpack2(a2p0), q1 = unpack2(a2p1);
  float acc2[4] = {q0.x, q0.y, q1.x, q1.y};

  #pragma unroll
  for (int tok = 0; tok < 4; tok++){
    float d0 = __shfl_sync(0xffffffffu, acc[tok], 0);
    float d1 = __shfl_sync(0xffffffffu, acc[tok], 1);
    #pragma unroll
    for (int kk = 0; kk < 2; kk++){
      int ch = lane + 32*kk;
      if (ch < DIN){
        float r = fmaf(w0c[kk], d0, fmaf(w1c[kk], d1, db[kk]));
        dt_s[ch][w*4+tok] = fmaxf(r, 0.f) + __logf(1.f + __expf(-fabsf(r)));
      }
    }
    if (lane >= 2) bc_s[lane-2][w*4+tok]  = acc[tok];
    else           bc_s[30+lane][w*4+tok] = acc2[tok];
  }
  __syncthreads();

  // coalesced flush: consecutive threads -> consecutive float4 along t
  for (int i = tid; i < DIN*8; i += 256){
    int ch = i >> 3, v = i & 7;
    int tt = tile0 + 4*v;
    size_t off = (size_t)(n*DIN + ch)*LFP + tt;
    *(float4*)(xsT + off) = make_float4(xs_s[ch][4*v],xs_s[ch][4*v+1],xs_s[ch][4*v+2],xs_s[ch][4*v+3]);
    *(float4*)(zsT + off) = make_float4(zs_s[ch][4*v],zs_s[ch][4*v+1],zs_s[ch][4*v+2],zs_s[ch][4*v+3]);
    *(float4*)(dtT + off) = make_float4(dt_s[ch][4*v],dt_s[ch][4*v+1],dt_s[ch][4*v+2],dt_s[ch][4*v+3]);
  }
  // bc interleaved flush: [n][tb][comp][4]; one float4 per thread (8 tb x 32 comp)
  {
    int tbl = tid >> 5, comp = tid & 31;
    float4 bv = make_float4(bc_s[comp][4*tbl],bc_s[comp][4*tbl+1],bc_s[comp][4*tbl+2],bc_s[comp][4*tbl+3]);
    *(float4*)(bcI + ((size_t)(n*(LFP/4) + tile0/4 + tbl)*32 + comp)*4) = bv;
  }
}

// ============ K3: selective scan (coalesced B/C, buffered y stores) ============
template<int L, int DIN, int LFP, int LT>
__device__ __forceinline__ void scan_seq(
  const float* __restrict__ dtT, const float* __restrict__ xsT,
  const float* __restrict__ zsT, const float* __restrict__ bcI,
  float* __restrict__ yT, const float* __restrict__ alog,
  const float* __restrict__ Dv, int n, int ch2, int lane)
{
  int half = lane >> 4, s = lane & 15;
  int ch = ch2 + half;
  const float* dtp = dtT + (size_t)(n*DIN + ch)*LFP;
  const float* xsp = xsT + (size_t)(n*DIN + ch)*LFP;
  const float* zsp = zsT + (size_t)(n*DIN + ch)*LFP;
  const float* bcn = bcI + (size_t)n*(LFP/4)*128;
  float A  = -expf(__ldg(alog + ch*16 + s));
  float Dd = __ldg(Dv + ch);
  float* yTp = yT + (size_t)(n*DIN + ch)*LT;
  bool yl = (s == 0);
  float h = 0.f;
  float yb0=0.f, yb1=0.f, yb2=0.f;
  constexpr int NB = (L-1)/4;
  for (int tb = 0; tb < NB; tb++){
    int t = tb*4;
    float4 dq = __ldg((const float4*)(dtp + t));
    float4 uq = __ldg((const float4*)(xsp + t));
    float4 Bq = __ldg((const float4*)(bcn + tb*128 + s*4));
    float4 Cq = __ldg((const float4*)(bcn + tb*128 + 64 + s*4));
    float4 zv = make_float4(0,0,0,0);
    if (yl) zv = __ldg((const float4*)(zsp + t));
    float da[4] = {dq.x,dq.y,dq.z,dq.w};
    float ua[4] = {uq.x,uq.y,uq.z,uq.w};
    float Ba[4] = {Bq.x,Bq.y,Bq.z,Bq.w};
    float Ca[4] = {Cq.x,Cq.y,Cq.z,Cq.w};
    float za[4] = {zv.x,zv.y,zv.z,zv.w};
    #pragma unroll
    for (int j = 0; j < 4; j++){
      float a = __expf(da[j]*A);
      h = fmaf(h, a, da[j]*ua[j]*Ba[j]);
      float acc = h * Ca[j];
      acc += __shfl_xor_sync(0xffffffffu, acc, 1);
      acc += __shfl_xor_sync(0xffffffffu, acc, 2);
      acc += __shfl_xor_sync(0xffffffffu, acc, 4);
      acc += __shfl_xor_sync(0xffffffffu, acc, 8);
      if (yl){
        float val = fmaf(ua[j], Dd, acc) * za[j];
        if (j == 0){
          if (tb > 0) *(float4*)(yTp + t - 4) = make_float4(yb0, yb1, yb2, val);
        } else if (j == 1) yb0 = val;
        else if (j == 2)   yb1 = val;
        else               yb2 = val;
      }
    }
  }
  { // tail t = L-1 (tt = L-2, slot 3)
    constexpr int t = L-1;
    float dtv = __ldg(dtp + t), u = __ldg(xsp + t);
    float Bv = __ldg(bcn + NB*128 + s*4);
    float Cv = __ldg(bcn + NB*128 + 64 + s*4);
    float a = __expf(dtv*A);
    h = fmaf(h, a, dtv*u*Bv);
    float acc = h * Cv;
    acc += __shfl_xor_sync(0xffffffffu, acc, 1);
    acc += __shfl_xor_sync(0xffffffffu, acc, 2);
    acc += __shfl_xor_sync(0xffffffffu, acc, 4);
    acc += __shfl_xor_sync(0xffffffffu, acc, 8);
    if (yl){
      float val = fmaf(u, Dd, acc) * __ldg(zsp + t);
      *(float4*)(yTp + L - 5) = make_float4(yb0, yb1, yb2, val);
    }
  }
}

__global__ void __launch_bounds__(256) k_scan(
  const float* __restrict__ alogA, const float* __restrict__ DA,
  const float* __restrict__ alogB, const float* __restrict__ DB)
{
  int wg = (blockIdx.x*256 + threadIdx.x) >> 5;   // 0..5119
  int lane = threadIdx.x & 31;
  if (wg < 2048){
    int n = wg >> 5, ch2 = (wg & 31)*2;
    scan_seq<LA,64,LPA,LTA>(gA_dtT, gA_xsT, gA_zsT, gA_bcI, gA_yT, alogA, DA, n, ch2, lane);
  } else {
    int w2 = wg - 2048;
    if (w2 < 1536){
      int n = w2/24, ch2 = (w2 - n*24)*2;
      scan_seq<LB,48,LPB,LTB>(gB_dtT0, gB_xsT0, gB_zsT0, gB_bcI0, gB_yT0, alogB, DB, n, ch2, lane);
    } else {
      w2 -= 1536;
      int n = w2/24, ch2 = (w2 - n*24)*2;
      scan_seq<LB,48,LPB,LTB>(gB_dtT1, gB_xsT1, gB_zsT1, gB_bcI1, gB_yT1, alogB, DB, n, ch2, lane);
    }
  }
}

// ============ K4: out_proj (transposed y via smem tile, FFMA2) ============
template<int RUN>
__global__ void __launch_bounds__(256) k_outproj(const float* __restrict__ Wo)
{
  constexpr int DIN = (RUN==0)?64:48;
  constexpr int DM  = (RUN==0)?32:24;
  constexpr int LT  = (RUN==0)?LTA:LTB;
  const float* yT = bufYT<RUN>();
  float* o = bufO<RUN>();
  __shared__ float Wt[DIN*32];
  __shared__ __align__(16) float y_s[DIN][34];
  int tid = threadIdx.x;
  for (int i = tid; i < DIN*32; i += 256){
    int d = i >> 5, oo = i & 31;
    Wt[i] = (oo < DM) ? Wo[oo*DIN + d] : 0.f;
  }
  int w = tid >> 5, lane = tid & 31;
  int n = blockIdx.y;
  int tile0 = blockIdx.x*32;
  for (int i = tid; i < DIN*8; i += 256){
    int ch = i >> 3, v = i & 7;
    float4 yv = *(const float4*)(yT + (size_t)(n*DIN + ch)*LT + tile0 + 4*v);
    y_s[ch][4*v+0] = yv.x; y_s[ch][4*v+1] = yv.y;
    y_s[ch][4*v+2] = yv.z; y_s[ch][4*v+3] = yv.w;
  }
  __syncthreads();
  unsigned long long ap0=0ull, ap1=0ull;
  #pragma unroll 8
  for (int d = 0; d < DIN; d++){
    const unsigned long long* yp2 = (const unsigned long long*)&y_s[d][w*4];
    unsigned long long y01 = yp2[0], y23 = yp2[1];
    float wv = Wt[d*32 + lane];
    unsigned long long wp = pack2(wv, wv);
    ffma2(ap0, wp, y01);
    ffma2(ap1, wp, y23);
  }
  float2 u0 = unpack2(ap0), u1 = unpack2(ap1);
  float acc[4] = {u0.x, u0.y, u1.x, u1.y};
  if (lane < DM){
    #pragma unroll
    for (int tok = 0; tok < 4; tok++){
      int t = tile0 + w*4 + tok;
      o[(size_t)(n*LT + t)*DM + lane] = acc[tok];
    }
  }
}

// ============ K5: combine into output ============
__global__ void __launch_bounds__(256) k_combine(float* __restrict__ out)
{
  int idx = blockIdx.x*256 + threadIdx.x;
  if (idx >= 128*192*192) return;
  int c = idx / 36864;
  int rem = idx - c*36864;
  int n = rem / 576;
  int rem2 = rem - n*576;
  int i = rem2 / 24;
  int j = rem2 - i*24;
  int d = c >> 2, r1 = (c >> 1) & 1, r2 = c & 1;
  float v0 = gA_o [(size_t)(n*2304 + (2*i+r1)*48 + 2*j + r2)*32 + d];
  float v1 = gB_o0[(size_t)(n*3072 + c*24 + j)*24 + i];
  float v2 = gB_o1[(size_t)(n*3072 + c*24 + i)*24 + j];
  out[idx] = (v0 + v1 + v2) * (1.f/3.f);
}

// ============ host launch ============
extern "C" void kernel_launch(void* const* d_in, const int* in_sizes, int n_in,
                              void* d_out, int out_size) {
  (void)in_sizes; (void)n_in; (void)out_size;
  const float* X   = (const float*)d_in[0];
  const float* NW  = (const float*)d_in[1];
  const float* NB  = (const float*)d_in[2];
  const float* N2W = (const float*)d_in[3];
  const float* N2B = (const float*)d_in[4];
  const float* GT1 = (const float*)d_in[5];
  const float* GT2 = (const float*)d_in[6];
  const float* M1_IN  = (const float*)d_in[7];
  const float* M1_CW  = (const float*)d_in[8];
  const float* M1_CB  = (const float*)d_in[9];
  const float* M1_XW  = (const float*)d_in[10];
  const float* M1_DTW = (const float*)d_in[11];
  const float* M1_DTB = (const float*)d_in[12];
  const float* M1_AL  = (const float*)d_in[13];
  const float* M1_D   = (const float*)d_in[14];
  const float* M1_OW  = (const float*)d_in[15];
  const float* M2_IN  = (const float*)d_in[16];
  const float* M2_CW  = (const float*)d_in[17];
  const float* M2_CB  = (const float*)d_in[18];
  const float* M2_XW  = (const float*)d_in[19];
  const float* M2_DTW = (const float*)d_in[20];
  const float* M2_DTB = (const float*)d_in[21];
  const float* M2_AL  = (const float*)d_in[22];
  const float* M2_D   = (const float*)d_in[23];
  const float* M2_OW  = (const float*)d_in[24];

  k_inproj<0><<<dim3(73, 64), 128>>>(X, NW,  NB,  GT1, M1_IN);
  k_inproj<1><<<dim3(97, 64), 128>>>(X, N2W, N2B, GT2, M2_IN);
  k_inproj<2><<<dim3(97, 64), 128>>>(X, N2W, N2B, GT2, M2_IN);

  k_convxp<0><<<dim3(73, 64), 256>>>(M1_CW, M1_CB, M1_XW, M1_DTW, M1_DTB);
  k_convxp<1><<<dim3(97, 64), 256>>>(M2_CW, M2_CB, M2_XW, M2_DTW, M2_DTB);
  k_convxp<2><<<dim3(97, 64), 256>>>(M2_CW, M2_CB, M2_XW, M2_DTW, M2_DTB);

  k_scan<<<640, 256>>>(M1_AL, M1_D, M2_AL, M2_D);

  k_outproj<0><<<dim3(72, 64), 256>>>(M1_OW);
  k_outproj<1><<<dim3(96, 64), 256>>>(M2_OW);
  k_outproj<2><<<dim3(96, 64), 256>>>(M2_OW);

  k_combine<<<18432, 256>>>((float*)d_out);
}